// round 12
// baseline (speedup 1.0000x reference)
#include <cuda_runtime.h>
#include <cuda_fp16.h>
#include <cstdint>

#define BB 32
#define NN 512
#define DINN 768
#define DOUTT 256
#define NEGV -9.0e15f
#define SLOPE 0.2f

// ---------------------------------------------------------------------------
// Scratch (allocation-free). Referenced ONLY in device code.
// ---------------------------------------------------------------------------
__device__ __half g_WT[DOUTT * DINN];                   // W^T fp16 [dout][din]
__device__ __half g_WhT[(long)BB * DOUTT * NN];         // Wh^T fp16 [b][dout][node]
__device__ __half g_att[(long)BB * NN * NN];            // att fp16 [b][i][j]
__device__ float g_s1[BB * NN];
__device__ float g_s2[BB * NN];

// ---------------------------------------------------------------------------
__device__ __forceinline__ uint32_t smem_u32(const void* p) {
    uint32_t a;
    asm("{ .reg .u64 t; cvta.to.shared.u64 t, %1; cvt.u32.u64 %0, t; }" : "=r"(a) : "l"(p));
    return a;
}
__device__ __forceinline__ uint32_t pk2h(float a, float b) {
    __half2 hh = __floats2half2_rn(a, b);
    return *(uint32_t*)&hh;
}
__device__ __forceinline__ void cpa16(uint32_t s, const void* g) {
    asm volatile("cp.async.cg.shared.global [%0], [%1], 16;" :: "r"(s), "l"(g));
}

#define LDSM_X4(R, A)                                                         \
    asm volatile("ldmatrix.sync.aligned.m8n8.x4.shared.b16 {%0,%1,%2,%3}, [%4];" \
        : "=r"((R)[0]), "=r"((R)[1]), "=r"((R)[2]), "=r"((R)[3]) : "r"(A))

#define MMA16816(D, A, B0, B1)                                                \
    asm volatile("mma.sync.aligned.m16n8k16.row.col.f32.f16.f16.f32 "         \
        "{%0,%1,%2,%3},{%4,%5,%6,%7},{%8,%9},{%0,%1,%2,%3};"                  \
        : "+f"((D)[0]), "+f"((D)[1]), "+f"((D)[2]), "+f"((D)[3])              \
        : "r"((A)[0]), "r"((A)[1]), "r"((A)[2]), "r"((A)[3]), "r"(B0), "r"(B1))

// Stage layout (both GEMMs): A(32x32 fp16) | B(256x32 fp16), rows stride 80 B
#define S_A    0
#define S_B    2560
#define S_BUF  23040
#define NSTG   3
#define RING   (NSTG * S_BUF)      // 69120
#define G1_SMEM (RING + 128)       // + pos_s
#define G2_SMEM RING
#define STG1 36      // G1 stage: st[dout*36 + node], 256x32 fp32 (36864 B)
#define STG2 264     // G2 stage: st[node*264 + dout], 32x256 fp32 (33792 B)

// ---------------------------------------------------------------------------
// Pre-pass: W [din][dout] fp32 -> W^T fp16 [dout][din]
// ---------------------------------------------------------------------------
__global__ __launch_bounds__(256)
void k_transW(const float* __restrict__ W)
{
    __shared__ float t[32][33];
    const int k0 = blockIdx.x * 32, n0 = blockIdx.y * 32;
    const int tx = threadIdx.x & 31, ty = threadIdx.x >> 5;
    #pragma unroll
    for (int j = 0; j < 4; j++) {
        int r = ty + j * 8;
        t[r][tx] = W[(long)(k0 + r) * DOUTT + n0 + tx];
    }
    __syncthreads();
    #pragma unroll
    for (int j = 0; j < 4; j++) {
        int r = ty + j * 8;
        g_WT[(long)(n0 + r) * DINN + k0 + tx] = __float2half_rn(t[tx][r]);
    }
}

// ---------------------------------------------------------------------------
// GEMM1: D[32 x 256] = h[32xK] * W^T, K=768, single fp16 product.
// grid (NN/32=16, BB) = 512 CTAs; 8 warps of 32x32; 3-stage ring.
// A converted fp32->fp16 inline (1 float4/thread/stage); B via cp.async.
// Epilogue: WhT fp16 + fused s1/s2.
// ---------------------------------------------------------------------------
__global__ __launch_bounds__(256, 3)
void g1_gemm(const float* __restrict__ hsrc,
             const int* __restrict__ pos, const float* __restrict__ pt,
             const float* __restrict__ a1v, const float* __restrict__ a2v)
{
    extern __shared__ char smem[];
    const uint32_t sbase = smem_u32(smem);
    const int tid = threadIdx.x, lane = tid & 31, wid = tid >> 5;
    const int b = blockIdx.y;
    const int rowBase = blockIdx.x * 32;

    float acc[2][4][4];
    #pragma unroll
    for (int i = 0; i < 2; i++)
        #pragma unroll
        for (int j = 0; j < 4; j++)
            #pragma unroll
            for (int r = 0; r < 4; r++) acc[i][j][r] = 0.f;

    const float* Abase = hsrc + ((long)b * NN + rowBase) * DINN;
    float4 fa;                                  // 1 float4 per thread per stage
    const int ar = tid >> 3, ac4 = tid & 7;     // A: row 0..31, float4 0..7

    auto ALOADR = [&](int kc) {
        fa = *(const float4*)(Abase + (long)ar * DINN + kc + ac4 * 4);
    };
    auto ASTORE = [&](int s) {
        *(uint2*)(smem + s * S_BUF + S_A + ar * 80 + ac4 * 8) =
            make_uint2(pk2h(fa.x, fa.y), pk2h(fa.z, fa.w));
    };
    auto ISSUE_B = [&](int kc, int s) {
        const uint32_t sb2 = sbase + s * S_BUF;
        #pragma unroll
        for (int i = 0; i < 4; i++) {           // B: 256 rows x 64 B
            int idx = i * 256 + tid;
            int r = idx >> 2, c4 = idx & 3;
            cpa16(sb2 + S_B + r * 80 + c4 * 16,
                  g_WT + (long)r * DINN + kc + c4 * 8);
        }
        asm volatile("cp.async.commit_group;" ::: "memory");
    };

    const int arow = (((lane >> 3) & 1) * 8 + (lane & 7)) * 80;
    const int brow = (wid * 32 + ((lane >> 3) & 1) * 8 + (lane & 7)) * 80;

    auto COMPUTE = [&](int s) {
        const uint32_t base = sbase + s * S_BUF;
        #pragma unroll
        for (int k16 = 0; k16 < 2; k16++) {
            const int kb = (k16 * 16 + (lane >> 4) * 8) * 2;
            uint32_t af[2][4];
            #pragma unroll
            for (int am = 0; am < 2; am++)
                LDSM_X4(af[am], base + S_A + arow + am * 16 * 80 + kb);
            #pragma unroll
            for (int pr = 0; pr < 2; pr++) {
                uint32_t bh[4];
                LDSM_X4(bh, base + S_B + brow + pr * 16 * 80 + kb);
                #pragma unroll
                for (int od = 0; od < 2; od++) {
                    const int an = pr * 2 + od;
                    #pragma unroll
                    for (int am = 0; am < 2; am++)
                        MMA16816(acc[am][an], af[am], bh[od], bh[od + 2]);
                }
            }
        }
    };

    const int nT = DINN / 32;     // 24
    ALOADR(0);  ISSUE_B(0, 0);  ASTORE(0);
    ALOADR(32); ISSUE_B(32, 1); ASTORE(1);
    #pragma unroll 1
    for (int t = 0; t < nT; ++t) {
        if (t + 2 < nT) ALOADR((t + 2) * 32);
        if (t + 2 < nT) asm volatile("cp.async.wait_group 1;" ::: "memory");
        else            asm volatile("cp.async.wait_group 0;" ::: "memory");
        __syncthreads();
        if (t + 2 < nT) {
            ISSUE_B((t + 2) * 32, (t + 2) % 3);
            ASTORE((t + 2) % 3);
        }
        COMPUTE(t % 3);
    }
    __syncthreads();

    // ---- epilogue ----
    float* st  = (float*)smem;                 // [256 dout][36] fp32
    float* ps1 = (float*)(smem + 36864);       // [8][32]
    float* ps2 = (float*)(smem + 37888);
    int* pos_s = (int*)(smem + RING);          // 32 ints

    #pragma unroll
    for (int am = 0; am < 2; am++)
        #pragma unroll
        for (int an = 0; an < 4; an++) {
            const int r0 = am * 16 + (lane >> 2);           // node 0..31
            const int c0 = wid * 32 + an * 8 + (lane & 3) * 2;  // dout
            st[c0 * STG1 + r0]           = acc[am][an][0];
            st[(c0 + 1) * STG1 + r0]     = acc[am][an][1];
            st[c0 * STG1 + r0 + 8]       = acc[am][an][2];
            st[(c0 + 1) * STG1 + r0 + 8] = acc[am][an][3];
        }
    if (tid < 32) pos_s[tid] = pos[b * NN + rowBase + tid];
    __syncthreads();

    // pass A: add pos-emb, write WhT fp16 (coalesced over node), update stage
    #pragma unroll 4
    for (int i = 0; i < 32; i++) {
        int idx = i * 256 + tid;
        int dl = idx >> 5, nl = idx & 31;
        float v = st[dl * STG1 + nl] + __ldg(pt + (long)pos_s[nl] * DOUTT + dl);
        st[dl * STG1 + nl] = v;
        g_WhT[((long)b * DOUTT + dl) * NN + rowBase + nl] = __float2half_rn(v);
    }
    __syncthreads();

    // pass B: fused s1/s2 (8 partials per node)
    {
        const int node = tid & 31, q = tid >> 5;
        float v1 = 0.f, v2 = 0.f;
        #pragma unroll 4
        for (int c = 0; c < 32; c++) {
            int dl = q * 32 + c;
            float v = st[dl * STG1 + node];
            v1 += v * __ldg(a1v + dl);
            v2 += v * __ldg(a2v + dl);
        }
        ps1[q * 32 + node] = v1;
        ps2[q * 32 + node] = v2;
    }
    __syncthreads();
    if (tid < 32) {
        float s1 = 0.f, s2 = 0.f;
        #pragma unroll
        for (int q = 0; q < 8; q++) { s1 += ps1[q * 32 + tid]; s2 += ps2[q * 32 + tid]; }
        g_s1[b * NN + rowBase + tid] = s1;
        g_s2[b * NN + rowBase + tid] = s2;
    }
}

// ---------------------------------------------------------------------------
// GEMM2: hp[32 x 256] = att[32xK] * WhT, K=512, single fp16 product.
// grid (16, BB) = 512 CTAs; 8 warps of 32x32; 3-stage ring.
// ---------------------------------------------------------------------------
__global__ __launch_bounds__(256, 3)
void g2_gemm(float* __restrict__ hp)
{
    extern __shared__ char smem[];
    const uint32_t sbase = smem_u32(smem);
    const int tid = threadIdx.x, lane = tid & 31, wid = tid >> 5;
    const int b = blockIdx.y;
    const int rowBase = blockIdx.x * 32;

    float acc[2][4][4];
    #pragma unroll
    for (int i = 0; i < 2; i++)
        #pragma unroll
        for (int j = 0; j < 4; j++)
            #pragma unroll
            for (int r = 0; r < 4; r++) acc[i][j][r] = 0.f;

    auto ISSUE = [&](int kc, int s) {
        const uint32_t sb2 = sbase + s * S_BUF;
        if (tid < 128) {   // A: att 32 rows x 64 B
            int r = tid >> 2, c4 = tid & 3;
            long go = ((long)b * NN + rowBase + r) * NN + kc + c4 * 8;
            cpa16(sb2 + S_A + r * 80 + c4 * 16, g_att + go);
        }
        #pragma unroll
        for (int i = 0; i < 4; i++) {   // B: WhT 256 rows x 64 B
            int idx = i * 256 + tid;
            int r = idx >> 2, c4 = idx & 3;
            long go = ((long)b * DOUTT + r) * NN + kc + c4 * 8;
            cpa16(sb2 + S_B + r * 80 + c4 * 16, g_WhT + go);
        }
        asm volatile("cp.async.commit_group;" ::: "memory");
    };

    const int arow = (((lane >> 3) & 1) * 8 + (lane & 7)) * 80;
    const int brow = (wid * 32 + ((lane >> 3) & 1) * 8 + (lane & 7)) * 80;

    auto COMPUTE = [&](int s) {
        const uint32_t base = sbase + s * S_BUF;
        #pragma unroll
        for (int k16 = 0; k16 < 2; k16++) {
            const int kb = (k16 * 16 + (lane >> 4) * 8) * 2;
            uint32_t af[2][4];
            #pragma unroll
            for (int am = 0; am < 2; am++)
                LDSM_X4(af[am], base + S_A + arow + am * 16 * 80 + kb);
            #pragma unroll
            for (int pr = 0; pr < 2; pr++) {
                uint32_t bh[4];
                LDSM_X4(bh, base + S_B + brow + pr * 16 * 80 + kb);
                #pragma unroll
                for (int od = 0; od < 2; od++) {
                    const int an = pr * 2 + od;
                    #pragma unroll
                    for (int am = 0; am < 2; am++)
                        MMA16816(acc[am][an], af[am], bh[od], bh[od + 2]);
                }
            }
        }
    };

    const int nT = NN / 32;       // 16
    ISSUE(0, 0);
    ISSUE(32, 1);
    #pragma unroll 1
    for (int t = 0; t < nT; ++t) {
        if (t + 2 < nT) asm volatile("cp.async.wait_group 1;" ::: "memory");
        else            asm volatile("cp.async.wait_group 0;" ::: "memory");
        __syncthreads();
        if (t + 2 < nT) ISSUE((t + 2) * 32, (t + 2) % 3);
        COMPUTE(t % 3);
    }
    __syncthreads();

    // ---- epilogue: stage row-major, coalesced float4 out ----
    float* st = (float*)smem;                  // [32 node][264] fp32
    #pragma unroll
    for (int am = 0; am < 2; am++)
        #pragma unroll
        for (int an = 0; an < 4; an++) {
            const int r0 = am * 16 + (lane >> 2);
            const int c0 = wid * 32 + an * 8 + (lane & 3) * 2;
            st[r0 * STG2 + c0]           = acc[am][an][0];
            st[r0 * STG2 + c0 + 1]       = acc[am][an][1];
            st[(r0 + 8) * STG2 + c0]     = acc[am][an][2];
            st[(r0 + 8) * STG2 + c0 + 1] = acc[am][an][3];
        }
    __syncthreads();
    #pragma unroll 4
    for (int i = 0; i < 8; i++) {
        int fid = i * 256 + tid;
        int r = fid >> 6, c4 = fid & 63;
        float4 v = *(const float4*)&st[r * STG2 + c4 * 4];
        *(float4*)&hp[((long)b * NN + rowBase + r) * DOUTT + c4 * 4] = v;
    }
}

// ---------------------------------------------------------------------------
// Masked-softmax attention row: fp32 att to d_out + fp16 scratch.
// ---------------------------------------------------------------------------
__global__ __launch_bounds__(128)
void k_attn(const int* __restrict__ adj, float* __restrict__ att)
{
    const int i = blockIdx.x, b = blockIdx.y;
    const long base = ((long)b * NN + i) * NN;
    const int t = threadIdx.x;
    const float s1v = g_s1[b * NN + i];

    const int4   a4 = *(const int4*)(adj + base + t * 4);
    const float4 s2 = *(const float4*)(g_s2 + b * NN + t * 4);

    float e[4];
    {
        float x;
        x = s1v + s2.x; x = x > 0.f ? x : SLOPE * x; e[0] = (a4.x > 0) ? x : NEGV;
        x = s1v + s2.y; x = x > 0.f ? x : SLOPE * x; e[1] = (a4.y > 0) ? x : NEGV;
        x = s1v + s2.z; x = x > 0.f ? x : SLOPE * x; e[2] = (a4.z > 0) ? x : NEGV;
        x = s1v + s2.w; x = x > 0.f ? x : SLOPE * x; e[3] = (a4.w > 0) ? x : NEGV;
    }

    __shared__ float red[4];
    float m = fmaxf(fmaxf(e[0], e[1]), fmaxf(e[2], e[3]));
    #pragma unroll
    for (int o = 16; o; o >>= 1) m = fmaxf(m, __shfl_xor_sync(0xffffffffu, m, o));
    if ((t & 31) == 0) red[t >> 5] = m;
    __syncthreads();
    float M = fmaxf(fmaxf(red[0], red[1]), fmaxf(red[2], red[3]));
    __syncthreads();

    float x0 = __expf(e[0] - M), x1 = __expf(e[1] - M);
    float x2 = __expf(e[2] - M), x3 = __expf(e[3] - M);
    float s = (x0 + x1) + (x2 + x3);
    #pragma unroll
    for (int o = 16; o; o >>= 1) s += __shfl_xor_sync(0xffffffffu, s, o);
    if ((t & 31) == 0) red[t >> 5] = s;
    __syncthreads();
    float inv = 1.f / (red[0] + red[1] + red[2] + red[3]);

    float v0 = x0 * inv, v1 = x1 * inv, v2 = x2 * inv, v3 = x3 * inv;
    *(float4*)(att + base + t * 4) = make_float4(v0, v1, v2, v3);
    *(uint2*)(g_att + base + t * 4) = make_uint2(pk2h(v0, v1), pk2h(v2, v3));
}

// ---------------------------------------------------------------------------
extern "C" void kernel_launch(void* const* d_in, const int* in_sizes, int n_in,
                              void* d_out, int out_size)
{
    const float* h   = (const float*)d_in[0];
    const int*   adj = (const int*)  d_in[1];
    const int*   pos = (const int*)  d_in[2];
    const float* W   = (const float*)d_in[3];
    const float* a1  = (const float*)d_in[4];
    const float* a2  = (const float*)d_in[5];
    const float* pt  = (const float*)d_in[6];

    float* out = (float*)d_out;
    float* hp  = out;                              // [B,N,DOUT]
    float* att = out + (long)BB * NN * DOUTT;      // [B,N,N]

    static int smem_set = 0;
    if (!smem_set) {
        cudaFuncSetAttribute(g1_gemm, cudaFuncAttributeMaxDynamicSharedMemorySize, G1_SMEM);
        cudaFuncSetAttribute(g2_gemm, cudaFuncAttributeMaxDynamicSharedMemorySize, G2_SMEM);
        smem_set = 1;
    }

    dim3 gT(DINN / 32, DOUTT / 32);                // (24, 8)
    k_transW<<<gT, 256>>>(W);

    dim3 gG(NN / 32, BB);                          // (16, 32) = 512 CTAs
    g1_gemm<<<gG, 256, G1_SMEM>>>(h, pos, pt, a1, a2);

    dim3 g3(NN, BB);                               // (512, 32)
    k_attn<<<g3, 128>>>(adj, att);

    g2_gemm<<<gG, 256, G2_SMEM>>>(hp);
}

// round 13
// speedup vs baseline: 1.4691x; 1.4691x over previous
#include <cuda_runtime.h>
#include <cuda_fp16.h>
#include <cstdint>

#define BB 32
#define NN 512
#define DINN 768
#define DOUTT 256
#define NEGV -9.0e15f
#define SLOPE 0.2f

// ---------------------------------------------------------------------------
// Scratch (allocation-free). Referenced ONLY in device code.
// ---------------------------------------------------------------------------
__device__ __half g_WT[DOUTT * DINN];                   // W^T fp16 [dout][din]
__device__ __half g_WhT[(long)BB * DOUTT * NN];         // Wh^T fp16 [b][dout][node]
__device__ __half g_att[(long)BB * NN * NN];            // att fp16 [b][i][j]
__device__ float g_s1[BB * NN];
__device__ float g_s2[BB * NN];

// ---------------------------------------------------------------------------
__device__ __forceinline__ uint32_t smem_u32(const void* p) {
    uint32_t a;
    asm("{ .reg .u64 t; cvta.to.shared.u64 t, %1; cvt.u32.u64 %0, t; }" : "=r"(a) : "l"(p));
    return a;
}
__device__ __forceinline__ uint32_t pk2h(float a, float b) {
    __half2 hh = __floats2half2_rn(a, b);
    return *(uint32_t*)&hh;
}
__device__ __forceinline__ void cpa16(uint32_t s, const void* g) {
    asm volatile("cp.async.cg.shared.global [%0], [%1], 16;" :: "r"(s), "l"(g));
}

#define LDSM_X4(R, A)                                                         \
    asm volatile("ldmatrix.sync.aligned.m8n8.x4.shared.b16 {%0,%1,%2,%3}, [%4];" \
        : "=r"((R)[0]), "=r"((R)[1]), "=r"((R)[2]), "=r"((R)[3]) : "r"(A))

#define MMA16816(D, A, B0, B1)                                                \
    asm volatile("mma.sync.aligned.m16n8k16.row.col.f32.f16.f16.f32 "         \
        "{%0,%1,%2,%3},{%4,%5,%6,%7},{%8,%9},{%0,%1,%2,%3};"                  \
        : "+f"((D)[0]), "+f"((D)[1]), "+f"((D)[2]), "+f"((D)[3])              \
        : "r"((A)[0]), "r"((A)[1]), "r"((A)[2]), "r"((A)[3]), "r"(B0), "r"(B1))

// G1: A(64x32 fp16) | B(256x32 fp16), rows stride 80 B; 3 stages
#define G1_A   0
#define G1_BH  5120
#define G1_BUF 25600
#define G1_SMEM 77056          // 3 stages (76800) + pos_s(256); epi 69632 fits
// G2: A(64x32) | B(256x32); 3 stages
#define G2_A   0
#define G2_BH  5120
#define G2_BUF 25600
#define G2_SMEM 76800          // epilogue stage 67584 fits
#define STG1 68                // G1 stage: st[dout*68 + node], 256x64
#define STG2 264               // G2 stage: st[node*264 + dout], 64x256

// ---------------------------------------------------------------------------
// Pre-pass: W [din][dout] fp32 -> W^T fp16 [dout][din]
// ---------------------------------------------------------------------------
__global__ __launch_bounds__(256)
void k_transW(const float* __restrict__ W)
{
    __shared__ float t[32][33];
    const int k0 = blockIdx.x * 32, n0 = blockIdx.y * 32;
    const int tx = threadIdx.x & 31, ty = threadIdx.x >> 5;
    #pragma unroll
    for (int j = 0; j < 4; j++) {
        int r = ty + j * 8;
        t[r][tx] = W[(long)(k0 + r) * DOUTT + n0 + tx];
    }
    __syncthreads();
    #pragma unroll
    for (int j = 0; j < 4; j++) {
        int r = ty + j * 8;
        g_WT[(long)(n0 + r) * DINN + k0 + tx] = __float2half_rn(t[tx][r]);
    }
}

// ---------------------------------------------------------------------------
// GEMM1: D[64 x 256] = h[64xK] * W^T, K=768, single fp16 product.
// A converted fp32->fp16 inline (register-staged); B via cp.async; 3 stages.
// Epilogue: WhT fp16 + fused s1/s2. grid (8, BB) = 256 CTAs; 8 warps 64x32.
// ---------------------------------------------------------------------------
__global__ __launch_bounds__(256, 2)
void g1_gemm(const float* __restrict__ hsrc,
             const int* __restrict__ pos, const float* __restrict__ pt,
             const float* __restrict__ a1v, const float* __restrict__ a2v)
{
    extern __shared__ char smem[];
    const uint32_t sbase = smem_u32(smem);
    const int tid = threadIdx.x, lane = tid & 31, wid = tid >> 5;
    const int b = blockIdx.y;
    const int rowBase = blockIdx.x * 64;

    float acc[4][4][4];
    #pragma unroll
    for (int i = 0; i < 4; i++)
        #pragma unroll
        for (int j = 0; j < 4; j++)
            #pragma unroll
            for (int r = 0; r < 4; r++) acc[i][j][r] = 0.f;

    // A register staging: 2 float4 per thread per stage
    const float* Abase = hsrc + ((long)b * NN + rowBase) * DINN;
    float4 fa[2];

    auto ALOADR = [&](int kc) {
        #pragma unroll
        for (int i = 0; i < 2; i++) {
            int idx = i * 256 + tid;
            int r = idx >> 3, c4 = idx & 7;
            fa[i] = *(const float4*)(Abase + (long)r * DINN + kc + c4 * 4);
        }
    };
    auto ASTORE = [&](int s) {
        char* bufc = smem + s * G1_BUF;
        #pragma unroll
        for (int i = 0; i < 2; i++) {
            int idx = i * 256 + tid;
            int r = idx >> 3, c4 = idx & 7;
            *(uint2*)(bufc + G1_A + r * 80 + c4 * 8) =
                make_uint2(pk2h(fa[i].x, fa[i].y), pk2h(fa[i].z, fa[i].w));
        }
    };
    auto ISSUE_B = [&](int kc, int s) {
        const uint32_t sb2 = sbase + s * G1_BUF;
        #pragma unroll
        for (int i = 0; i < 4; i++) {   // B: 256 rows x 64 B
            int idx = i * 256 + tid;
            int r = idx >> 2, c4 = idx & 3;
            cpa16(sb2 + G1_BH + r * 80 + c4 * 16,
                  g_WT + (long)r * DINN + kc + c4 * 8);
        }
        asm volatile("cp.async.commit_group;" ::: "memory");
    };

    const int arow = (((lane >> 3) & 1) * 8 + (lane & 7)) * 80;
    const int brow = (wid * 32 + ((lane >> 3) & 1) * 8 + (lane & 7)) * 80;

    auto COMPUTE = [&](int s) {
        const uint32_t base = sbase + s * G1_BUF;
        #pragma unroll
        for (int k16 = 0; k16 < 2; k16++) {
            const int kb = (k16 * 16 + (lane >> 4) * 8) * 2;
            uint32_t af[4][4];
            #pragma unroll
            for (int am = 0; am < 4; am++)
                LDSM_X4(af[am], base + G1_A + arow + am * 16 * 80 + kb);
            #pragma unroll
            for (int pr = 0; pr < 2; pr++) {
                uint32_t bh[4];
                LDSM_X4(bh, base + G1_BH + brow + pr * 16 * 80 + kb);
                #pragma unroll
                for (int od = 0; od < 2; od++) {
                    const int an = pr * 2 + od;
                    #pragma unroll
                    for (int am = 0; am < 4; am++)
                        MMA16816(acc[am][an], af[am], bh[od], bh[od + 2]);
                }
            }
        }
    };

    // 3-stage ring, one sync per iter. Stage (t+2)%3 is free after iter-t sync
    // (COMPUTE(t-1) read it and every warp passed the barrier since).
    const int nT = DINN / 32;     // 24
    ALOADR(0);  ISSUE_B(0, 0);  ASTORE(0);
    ALOADR(32); ISSUE_B(32, 1); ASTORE(1);
    #pragma unroll 1
    for (int t = 0; t < nT; ++t) {
        if (t + 2 < nT) ALOADR((t + 2) * 32);
        if (t + 2 < nT) asm volatile("cp.async.wait_group 1;" ::: "memory");
        else            asm volatile("cp.async.wait_group 0;" ::: "memory");
        __syncthreads();
        if (t + 2 < nT) {
            ISSUE_B((t + 2) * 32, (t + 2) % 3);
            ASTORE((t + 2) % 3);
        }
        COMPUTE(t % 3);
    }
    __syncthreads();

    // ---- epilogue ----
    float* st  = (float*)smem;                 // [256 dout][68] x fp32
    float* ps1 = (float*)(smem + 69632);       // [4][64]
    float* ps2 = (float*)(smem + 70656);
    int* pos_s = (int*)(smem + 3 * G1_BUF);    // 64 ints

    #pragma unroll
    for (int am = 0; am < 4; am++)
        #pragma unroll
        for (int an = 0; an < 4; an++) {
            const int r0 = am * 16 + (lane >> 2);
            const int c0 = wid * 32 + an * 8 + (lane & 3) * 2;
            st[c0 * STG1 + r0]           = acc[am][an][0];
            st[(c0 + 1) * STG1 + r0]     = acc[am][an][1];
            st[c0 * STG1 + r0 + 8]       = acc[am][an][2];
            st[(c0 + 1) * STG1 + r0 + 8] = acc[am][an][3];
        }
    if (tid < 64) pos_s[tid] = pos[b * NN + rowBase + tid];
    __syncthreads();

    // pass A: add pos-emb, write WhT fp16, update stage
    #pragma unroll 2
    for (int i = 0; i < 64; i++) {
        int idx = i * 256 + tid;
        int dl = idx >> 6, nl = idx & 63;
        float v = st[dl * STG1 + nl] + __ldg(pt + (long)pos_s[nl] * DOUTT + dl);
        st[dl * STG1 + nl] = v;
        g_WhT[((long)b * DOUTT + dl) * NN + rowBase + nl] = __float2half_rn(v);
    }
    __syncthreads();

    // pass B: fused s1/s2
    {
        const int node = tid & 63, q = tid >> 6;
        float v1 = 0.f, v2 = 0.f;
        #pragma unroll 4
        for (int c = 0; c < 64; c++) {
            int dl = q * 64 + c;
            float v = st[dl * STG1 + node];
            v1 += v * __ldg(a1v + dl);
            v2 += v * __ldg(a2v + dl);
        }
        ps1[q * 64 + node] = v1;
        ps2[q * 64 + node] = v2;
    }
    __syncthreads();
    if (tid < 64) {
        float s1 = ps1[tid] + ps1[64 + tid] + ps1[128 + tid] + ps1[192 + tid];
        float s2 = ps2[tid] + ps2[64 + tid] + ps2[128 + tid] + ps2[192 + tid];
        g_s1[b * NN + rowBase + tid] = s1;
        g_s2[b * NN + rowBase + tid] = s2;
    }
}

// ---------------------------------------------------------------------------
// GEMM2: hp[64 x 256] = att[64xK] * WhT, K=512, single fp16 product.
// 3-stage ring, one sync/iter. grid (8, BB); 8 warps of 64x32.
// ---------------------------------------------------------------------------
__global__ __launch_bounds__(256, 2)
void g2_gemm(float* __restrict__ hp)
{
    extern __shared__ char smem[];
    const uint32_t sbase = smem_u32(smem);
    const int tid = threadIdx.x, lane = tid & 31, wid = tid >> 5;
    const int b = blockIdx.y;
    const int rowBase = blockIdx.x * 64;

    float acc[4][4][4];
    #pragma unroll
    for (int i = 0; i < 4; i++)
        #pragma unroll
        for (int j = 0; j < 4; j++)
            #pragma unroll
            for (int r = 0; r < 4; r++) acc[i][j][r] = 0.f;

    auto ISSUE = [&](int kc, int s) {
        const uint32_t sb2 = sbase + s * G2_BUF;
        {   // A: att 64 rows x 64 B
            int r = tid >> 2, c4 = tid & 3;
            long go = ((long)b * NN + rowBase + r) * NN + kc + c4 * 8;
            cpa16(sb2 + G2_A + r * 80 + c4 * 16, g_att + go);
        }
        #pragma unroll
        for (int i = 0; i < 4; i++) {   // B: WhT 256 rows x 64 B
            int idx = i * 256 + tid;
            int r = idx >> 2, c4 = idx & 3;
            long go = ((long)b * DOUTT + r) * NN + kc + c4 * 8;
            cpa16(sb2 + G2_BH + r * 80 + c4 * 16, g_WhT + go);
        }
        asm volatile("cp.async.commit_group;" ::: "memory");
    };

    const int arow = (((lane >> 3) & 1) * 8 + (lane & 7)) * 80;
    const int brow = (wid * 32 + ((lane >> 3) & 1) * 8 + (lane & 7)) * 80;

    auto COMPUTE = [&](int s) {
        const uint32_t base = sbase + s * G2_BUF;
        #pragma unroll
        for (int k16 = 0; k16 < 2; k16++) {
            const int kb = (k16 * 16 + (lane >> 4) * 8) * 2;
            uint32_t af[4][4];
            #pragma unroll
            for (int am = 0; am < 4; am++)
                LDSM_X4(af[am], base + G2_A + arow + am * 16 * 80 + kb);
            #pragma unroll
            for (int pr = 0; pr < 2; pr++) {
                uint32_t bh[4];
                LDSM_X4(bh, base + G2_BH + brow + pr * 16 * 80 + kb);
                #pragma unroll
                for (int od = 0; od < 2; od++) {
                    const int an = pr * 2 + od;
                    #pragma unroll
                    for (int am = 0; am < 4; am++)
                        MMA16816(acc[am][an], af[am], bh[od], bh[od + 2]);
                }
            }
        }
    };

    const int nT = NN / 32;       // 16
    ISSUE(0, 0);
    ISSUE(32, 1);
    #pragma unroll 1
    for (int t = 0; t < nT; ++t) {
        if (t + 2 < nT) asm volatile("cp.async.wait_group 1;" ::: "memory");
        else            asm volatile("cp.async.wait_group 0;" ::: "memory");
        __syncthreads();
        if (t + 2 < nT) ISSUE((t + 2) * 32, (t + 2) % 3);
        COMPUTE(t % 3);
    }
    __syncthreads();

    // ---- epilogue: stage row-major, coalesced float4 out ----
    float* st = (float*)smem;
    #pragma unroll
    for (int am = 0; am < 4; am++)
        #pragma unroll
        for (int an = 0; an < 4; an++) {
            const int r0 = am * 16 + (lane >> 2);
            const int c0 = wid * 32 + an * 8 + (lane & 3) * 2;
            st[r0 * STG2 + c0]           = acc[am][an][0];
            st[r0 * STG2 + c0 + 1]       = acc[am][an][1];
            st[(r0 + 8) * STG2 + c0]     = acc[am][an][2];
            st[(r0 + 8) * STG2 + c0 + 1] = acc[am][an][3];
        }
    __syncthreads();
    #pragma unroll 4
    for (int i = 0; i < 16; i++) {
        int fid = i * 256 + tid;
        int r = fid >> 6, c4 = fid & 63;
        float4 v = *(const float4*)&st[r * STG2 + c4 * 4];
        *(float4*)&hp[((long)b * NN + rowBase + r) * DOUTT + c4 * 4] = v;
    }
}

// ---------------------------------------------------------------------------
// Masked-softmax attention row: fp32 att to d_out + fp16 scratch.
// ---------------------------------------------------------------------------
__global__ __launch_bounds__(128)
void k_attn(const int* __restrict__ adj, float* __restrict__ att)
{
    const int i = blockIdx.x, b = blockIdx.y;
    const long base = ((long)b * NN + i) * NN;
    const int t = threadIdx.x;
    const float s1v = g_s1[b * NN + i];

    const int4   a4 = *(const int4*)(adj + base + t * 4);
    const float4 s2 = *(const float4*)(g_s2 + b * NN + t * 4);

    float e[4];
    {
        float x;
        x = s1v + s2.x; x = x > 0.f ? x : SLOPE * x; e[0] = (a4.x > 0) ? x : NEGV;
        x = s1v + s2.y; x = x > 0.f ? x : SLOPE * x; e[1] = (a4.y > 0) ? x : NEGV;
        x = s1v + s2.z; x = x > 0.f ? x : SLOPE * x; e[2] = (a4.z > 0) ? x : NEGV;
        x = s1v + s2.w; x = x > 0.f ? x : SLOPE * x; e[3] = (a4.w > 0) ? x : NEGV;
    }

    __shared__ float red[4];
    float m = fmaxf(fmaxf(e[0], e[1]), fmaxf(e[2], e[3]));
    #pragma unroll
    for (int o = 16; o; o >>= 1) m = fmaxf(m, __shfl_xor_sync(0xffffffffu, m, o));
    if ((t & 31) == 0) red[t >> 5] = m;
    __syncthreads();
    float M = fmaxf(fmaxf(red[0], red[1]), fmaxf(red[2], red[3]));
    __syncthreads();

    float x0 = __expf(e[0] - M), x1 = __expf(e[1] - M);
    float x2 = __expf(e[2] - M), x3 = __expf(e[3] - M);
    float s = (x0 + x1) + (x2 + x3);
    #pragma unroll
    for (int o = 16; o; o >>= 1) s += __shfl_xor_sync(0xffffffffu, s, o);
    if ((t & 31) == 0) red[t >> 5] = s;
    __syncthreads();
    float inv = 1.f / (red[0] + red[1] + red[2] + red[3]);

    float v0 = x0 * inv, v1 = x1 * inv, v2 = x2 * inv, v3 = x3 * inv;
    *(float4*)(att + base + t * 4) = make_float4(v0, v1, v2, v3);
    *(uint2*)(g_att + base + t * 4) = make_uint2(pk2h(v0, v1), pk2h(v2, v3));
}

// ---------------------------------------------------------------------------
extern "C" void kernel_launch(void* const* d_in, const int* in_sizes, int n_in,
                              void* d_out, int out_size)
{
    const float* h   = (const float*)d_in[0];
    const int*   adj = (const int*)  d_in[1];
    const int*   pos = (const int*)  d_in[2];
    const float* W   = (const float*)d_in[3];
    const float* a1  = (const float*)d_in[4];
    const float* a2  = (const float*)d_in[5];
    const float* pt  = (const float*)d_in[6];

    float* out = (float*)d_out;
    float* hp  = out;                              // [B,N,DOUT]
    float* att = out + (long)BB * NN * DOUTT;      // [B,N,N]

    static int smem_set = 0;
    if (!smem_set) {
        cudaFuncSetAttribute(g1_gemm, cudaFuncAttributeMaxDynamicSharedMemorySize, G1_SMEM);
        cudaFuncSetAttribute(g2_gemm, cudaFuncAttributeMaxDynamicSharedMemorySize, G2_SMEM);
        smem_set = 1;
    }

    dim3 gT(DINN / 32, DOUTT / 32);                // (24, 8)
    k_transW<<<gT, 256>>>(W);

    dim3 gG(NN / 64, BB);                          // (8, 32) = 256 CTAs
    g1_gemm<<<gG, 256, G1_SMEM>>>(h, pos, pt, a1, a2);

    dim3 g3(NN, BB);                               // (512, 32)
    k_attn<<<g3, 128>>>(adj, att);

    g2_gemm<<<gG, 256, G2_SMEM>>>(hp);
}

// round 14
// speedup vs baseline: 1.5122x; 1.0293x over previous
#include <cuda_runtime.h>
#include <cuda_fp16.h>
#include <cstdint>

#define BB 32
#define NN 512
#define DINN 768
#define DOUTT 256
#define NEGV -9.0e15f
#define SLOPE 0.2f

// ---------------------------------------------------------------------------
// Scratch (allocation-free). Referenced ONLY in device code.
// ---------------------------------------------------------------------------
__device__ __half g_WT[DOUTT * DINN];                   // W^T fp16 [dout][din]
__device__ __half g_WhT[(long)BB * DOUTT * NN];         // Wh^T fp16 [b][dout][node]
__device__ float g_s1[BB * NN];
__device__ float g_s2[BB * NN];

// ---------------------------------------------------------------------------
__device__ __forceinline__ uint32_t smem_u32(const void* p) {
    uint32_t a;
    asm("{ .reg .u64 t; cvta.to.shared.u64 t, %1; cvt.u32.u64 %0, t; }" : "=r"(a) : "l"(p));
    return a;
}
__device__ __forceinline__ uint32_t pk2h(float a, float b) {
    __half2 hh = __floats2half2_rn(a, b);
    return *(uint32_t*)&hh;
}
__device__ __forceinline__ void cpa16(uint32_t s, const void* g) {
    asm volatile("cp.async.cg.shared.global [%0], [%1], 16;" :: "r"(s), "l"(g));
}

#define LDSM_X4(R, A)                                                         \
    asm volatile("ldmatrix.sync.aligned.m8n8.x4.shared.b16 {%0,%1,%2,%3}, [%4];" \
        : "=r"((R)[0]), "=r"((R)[1]), "=r"((R)[2]), "=r"((R)[3]) : "r"(A))

#define MMA16816(D, A, B0, B1)                                                \
    asm volatile("mma.sync.aligned.m16n8k16.row.col.f32.f16.f16.f32 "         \
        "{%0,%1,%2,%3},{%4,%5,%6,%7},{%8,%9},{%0,%1,%2,%3};"                  \
        : "+f"((D)[0]), "+f"((D)[1]), "+f"((D)[2]), "+f"((D)[3])              \
        : "r"((A)[0]), "r"((A)[1]), "r"((A)[2]), "r"((A)[3]), "r"(B0), "r"(B1))

// G1: A(64x32 fp16) | B(256x32 fp16), rows stride 80 B; 3 stages
#define G1_A   0
#define G1_BH  5120
#define G1_BUF 25600
#define G1_SMEM 77056          // 3 stages (76800) + pos_s(256); epi 69632 fits
#define STG1 68                // G1 stage: st[dout*68 + node], 256x64

// G2 fused: A = full att tile 64x512 fp16, row stride 1040 B (conflict-free)
//           B ring: 2 stages x (256 rows x 32 k, stride 80 B)
#define F_SA    0
#define F_SAROW 1040
#define F_SB    66560
#define F_SBUF  20480
#define F_SS2   (F_SB + 2 * F_SBUF)      // 107520: s2[512] fp32
#define F_SS1   (F_SS2 + 2048)           // s1[64] fp32
#define G2_SMEM (F_SS1 + 256)            // 109824 -> 2 CTAs/SM
#define STG2 264               // epi stage: st[node*264 + dout], 64x256 (67584 B)

// ---------------------------------------------------------------------------
// Pre-pass: W [din][dout] fp32 -> W^T fp16 [dout][din]
// ---------------------------------------------------------------------------
__global__ __launch_bounds__(256)
void k_transW(const float* __restrict__ W)
{
    __shared__ float t[32][33];
    const int k0 = blockIdx.x * 32, n0 = blockIdx.y * 32;
    const int tx = threadIdx.x & 31, ty = threadIdx.x >> 5;
    #pragma unroll
    for (int j = 0; j < 4; j++) {
        int r = ty + j * 8;
        t[r][tx] = W[(long)(k0 + r) * DOUTT + n0 + tx];
    }
    __syncthreads();
    #pragma unroll
    for (int j = 0; j < 4; j++) {
        int r = ty + j * 8;
        g_WT[(long)(n0 + r) * DINN + k0 + tx] = __float2half_rn(t[tx][r]);
    }
}

// ---------------------------------------------------------------------------
// GEMM1: D[64 x 256] = h[64xK] * W^T, K=768, single fp16 product.
// (unchanged from R13 best)
// ---------------------------------------------------------------------------
__global__ __launch_bounds__(256, 2)
void g1_gemm(const float* __restrict__ hsrc,
             const int* __restrict__ pos, const float* __restrict__ pt,
             const float* __restrict__ a1v, const float* __restrict__ a2v)
{
    extern __shared__ char smem[];
    const uint32_t sbase = smem_u32(smem);
    const int tid = threadIdx.x, lane = tid & 31, wid = tid >> 5;
    const int b = blockIdx.y;
    const int rowBase = blockIdx.x * 64;

    float acc[4][4][4];
    #pragma unroll
    for (int i = 0; i < 4; i++)
        #pragma unroll
        for (int j = 0; j < 4; j++)
            #pragma unroll
            for (int r = 0; r < 4; r++) acc[i][j][r] = 0.f;

    const float* Abase = hsrc + ((long)b * NN + rowBase) * DINN;
    float4 fa[2];

    auto ALOADR = [&](int kc) {
        #pragma unroll
        for (int i = 0; i < 2; i++) {
            int idx = i * 256 + tid;
            int r = idx >> 3, c4 = idx & 7;
            fa[i] = *(const float4*)(Abase + (long)r * DINN + kc + c4 * 4);
        }
    };
    auto ASTORE = [&](int s) {
        char* bufc = smem + s * G1_BUF;
        #pragma unroll
        for (int i = 0; i < 2; i++) {
            int idx = i * 256 + tid;
            int r = idx >> 3, c4 = idx & 7;
            *(uint2*)(bufc + G1_A + r * 80 + c4 * 8) =
                make_uint2(pk2h(fa[i].x, fa[i].y), pk2h(fa[i].z, fa[i].w));
        }
    };
    auto ISSUE_B = [&](int kc, int s) {
        const uint32_t sb2 = sbase + s * G1_BUF;
        #pragma unroll
        for (int i = 0; i < 4; i++) {
            int idx = i * 256 + tid;
            int r = idx >> 2, c4 = idx & 3;
            cpa16(sb2 + G1_BH + r * 80 + c4 * 16,
                  g_WT + (long)r * DINN + kc + c4 * 8);
        }
        asm volatile("cp.async.commit_group;" ::: "memory");
    };

    const int arow = (((lane >> 3) & 1) * 8 + (lane & 7)) * 80;
    const int brow = (wid * 32 + ((lane >> 3) & 1) * 8 + (lane & 7)) * 80;

    auto COMPUTE = [&](int s) {
        const uint32_t base = sbase + s * G1_BUF;
        #pragma unroll
        for (int k16 = 0; k16 < 2; k16++) {
            const int kb = (k16 * 16 + (lane >> 4) * 8) * 2;
            uint32_t af[4][4];
            #pragma unroll
            for (int am = 0; am < 4; am++)
                LDSM_X4(af[am], base + G1_A + arow + am * 16 * 80 + kb);
            #pragma unroll
            for (int pr = 0; pr < 2; pr++) {
                uint32_t bh[4];
                LDSM_X4(bh, base + G1_BH + brow + pr * 16 * 80 + kb);
                #pragma unroll
                for (int od = 0; od < 2; od++) {
                    const int an = pr * 2 + od;
                    #pragma unroll
                    for (int am = 0; am < 4; am++)
                        MMA16816(acc[am][an], af[am], bh[od], bh[od + 2]);
                }
            }
        }
    };

    const int nT = DINN / 32;     // 24
    ALOADR(0);  ISSUE_B(0, 0);  ASTORE(0);
    ALOADR(32); ISSUE_B(32, 1); ASTORE(1);
    #pragma unroll 1
    for (int t = 0; t < nT; ++t) {
        if (t + 2 < nT) ALOADR((t + 2) * 32);
        if (t + 2 < nT) asm volatile("cp.async.wait_group 1;" ::: "memory");
        else            asm volatile("cp.async.wait_group 0;" ::: "memory");
        __syncthreads();
        if (t + 2 < nT) {
            ISSUE_B((t + 2) * 32, (t + 2) % 3);
            ASTORE((t + 2) % 3);
        }
        COMPUTE(t % 3);
    }
    __syncthreads();

    // ---- epilogue ----
    float* st  = (float*)smem;
    float* ps1 = (float*)(smem + 69632);
    float* ps2 = (float*)(smem + 70656);
    int* pos_s = (int*)(smem + 3 * G1_BUF);

    #pragma unroll
    for (int am = 0; am < 4; am++)
        #pragma unroll
        for (int an = 0; an < 4; an++) {
            const int r0 = am * 16 + (lane >> 2);
            const int c0 = wid * 32 + an * 8 + (lane & 3) * 2;
            st[c0 * STG1 + r0]           = acc[am][an][0];
            st[(c0 + 1) * STG1 + r0]     = acc[am][an][1];
            st[c0 * STG1 + r0 + 8]       = acc[am][an][2];
            st[(c0 + 1) * STG1 + r0 + 8] = acc[am][an][3];
        }
    if (tid < 64) pos_s[tid] = pos[b * NN + rowBase + tid];
    __syncthreads();

    #pragma unroll 2
    for (int i = 0; i < 64; i++) {
        int idx = i * 256 + tid;
        int dl = idx >> 6, nl = idx & 63;
        float v = st[dl * STG1 + nl] + __ldg(pt + (long)pos_s[nl] * DOUTT + dl);
        st[dl * STG1 + nl] = v;
        g_WhT[((long)b * DOUTT + dl) * NN + rowBase + nl] = __float2half_rn(v);
    }
    __syncthreads();

    {
        const int node = tid & 63, q = tid >> 6;
        float v1 = 0.f, v2 = 0.f;
        #pragma unroll 4
        for (int c = 0; c < 64; c++) {
            int dl = q * 64 + c;
            float v = st[dl * STG1 + node];
            v1 += v * __ldg(a1v + dl);
            v2 += v * __ldg(a2v + dl);
        }
        ps1[q * 64 + node] = v1;
        ps2[q * 64 + node] = v2;
    }
    __syncthreads();
    if (tid < 64) {
        float s1 = ps1[tid] + ps1[64 + tid] + ps1[128 + tid] + ps1[192 + tid];
        float s2 = ps2[tid] + ps2[64 + tid] + ps2[128 + tid] + ps2[192 + tid];
        g_s1[b * NN + rowBase + tid] = s1;
        g_s2[b * NN + rowBase + tid] = s2;
    }
}

// ---------------------------------------------------------------------------
// GEMM2 fused: softmax prologue (att rows 64x512 -> d_out fp32 + smem fp16),
// then hp[64x256] = att * WhT. B-only 2-stage ring. grid (8, BB).
// ---------------------------------------------------------------------------
__global__ __launch_bounds__(256, 2)
void g2_fused(const int* __restrict__ adj, float* __restrict__ att,
              float* __restrict__ hp)
{
    extern __shared__ char smem[];
    const uint32_t sbase = smem_u32(smem);
    const int tid = threadIdx.x, lane = tid & 31, wid = tid >> 5;
    const int b = blockIdx.y;
    const int rowBase = blockIdx.x * 64;

    auto ISSUE_B = [&](int kc, int s) {
        const uint32_t sb2 = sbase + F_SB + s * F_SBUF;
        #pragma unroll
        for (int i = 0; i < 4; i++) {   // B: WhT 256 rows x 64 B
            int idx = i * 256 + tid;
            int r = idx >> 2, c4 = idx & 3;
            long go = ((long)b * DOUTT + r) * NN + kc + c4 * 8;
            cpa16(sb2 + r * 80 + c4 * 16, g_WhT + go);
        }
        asm volatile("cp.async.commit_group;" ::: "memory");
    };

    // kick off first B stage before softmax so copies overlap it
    ISSUE_B(0, 0);

    // ---- softmax prologue: 8 warps x 8 rows ----
    float* s2s = (float*)(smem + F_SS2);
    float* s1s = (float*)(smem + F_SS1);
    if (tid < 128) ((float4*)s2s)[tid] = ((const float4*)(g_s2 + b * NN))[tid];
    if (tid < 64)  s1s[tid] = g_s1[b * NN + rowBase + tid];
    __syncthreads();

    #pragma unroll 1
    for (int rr = 0; rr < 8; rr++) {
        const int r = wid * 8 + rr;
        const long abase = ((long)b * NN + rowBase + r) * NN;
        const float s1v = s1s[r];
        float ev[4][4];
        float mx = -3.4e38f;
        #pragma unroll
        for (int c = 0; c < 4; c++) {
            const int j0 = c * 128 + lane * 4;
            int4 a4 = *(const int4*)(adj + abase + j0);
            float4 s2v = *(const float4*)(s2s + j0);
            float x;
            x = s1v + s2v.x; x = x > 0.f ? x : SLOPE * x; ev[c][0] = (a4.x > 0) ? x : NEGV;
            x = s1v + s2v.y; x = x > 0.f ? x : SLOPE * x; ev[c][1] = (a4.y > 0) ? x : NEGV;
            x = s1v + s2v.z; x = x > 0.f ? x : SLOPE * x; ev[c][2] = (a4.z > 0) ? x : NEGV;
            x = s1v + s2v.w; x = x > 0.f ? x : SLOPE * x; ev[c][3] = (a4.w > 0) ? x : NEGV;
            mx = fmaxf(mx, fmaxf(fmaxf(ev[c][0], ev[c][1]), fmaxf(ev[c][2], ev[c][3])));
        }
        #pragma unroll
        for (int o = 16; o; o >>= 1) mx = fmaxf(mx, __shfl_xor_sync(0xffffffffu, mx, o));
        float sum = 0.f;
        #pragma unroll
        for (int c = 0; c < 4; c++)
            #pragma unroll
            for (int u = 0; u < 4; u++) {
                ev[c][u] = __expf(ev[c][u] - mx);
                sum += ev[c][u];
            }
        #pragma unroll
        for (int o = 16; o; o >>= 1) sum += __shfl_xor_sync(0xffffffffu, sum, o);
        const float inv = 1.f / sum;
        #pragma unroll
        for (int c = 0; c < 4; c++) {
            const int j0 = c * 128 + lane * 4;
            float v0 = ev[c][0] * inv, v1 = ev[c][1] * inv;
            float v2 = ev[c][2] * inv, v3 = ev[c][3] * inv;
            *(float4*)(att + abase + j0) = make_float4(v0, v1, v2, v3);
            *(uint2*)(smem + F_SA + r * F_SAROW + j0 * 2) =
                make_uint2(pk2h(v0, v1), pk2h(v2, v3));
        }
    }
    __syncthreads();   // A tile complete

    // ---- mainloop: A from resident smem, B 2-stage ring ----
    float acc[4][4][4];
    #pragma unroll
    for (int i = 0; i < 4; i++)
        #pragma unroll
        for (int j = 0; j < 4; j++)
            #pragma unroll
            for (int r = 0; r < 4; r++) acc[i][j][r] = 0.f;

    const int arow = (((lane >> 3) & 1) * 8 + (lane & 7)) * F_SAROW;
    const int brow = (wid * 32 + ((lane >> 3) & 1) * 8 + (lane & 7)) * 80;

    auto COMPUTE = [&](int t, int s) {
        const uint32_t abase2 = sbase + F_SA + arow + t * 64;
        const uint32_t bbase  = sbase + F_SB + s * F_SBUF;
        #pragma unroll
        for (int k16 = 0; k16 < 2; k16++) {
            const int kb = (k16 * 16 + (lane >> 4) * 8) * 2;
            uint32_t af[4][4];
            #pragma unroll
            for (int am = 0; am < 4; am++)
                LDSM_X4(af[am], abase2 + am * 16 * F_SAROW + kb);
            #pragma unroll
            for (int pr = 0; pr < 2; pr++) {
                uint32_t bh[4];
                LDSM_X4(bh, bbase + brow + pr * 16 * 80 + kb);
                #pragma unroll
                for (int od = 0; od < 2; od++) {
                    const int an = pr * 2 + od;
                    #pragma unroll
                    for (int am = 0; am < 4; am++)
                        MMA16816(acc[am][an], af[am], bh[od], bh[od + 2]);
                }
            }
        }
    };

    const int nT = NN / 32;       // 16
    #pragma unroll 1
    for (int t = 0; t < nT; ++t) {
        asm volatile("cp.async.wait_group 0;" ::: "memory");
        __syncthreads();
        if (t + 1 < nT) ISSUE_B((t + 1) * 32, (t + 1) & 1);
        COMPUTE(t, t & 1);
    }
    __syncthreads();

    // ---- epilogue: stage row-major, coalesced float4 out ----
    float* st = (float*)smem;
    #pragma unroll
    for (int am = 0; am < 4; am++)
        #pragma unroll
        for (int an = 0; an < 4; an++) {
            const int r0 = am * 16 + (lane >> 2);
            const int c0 = wid * 32 + an * 8 + (lane & 3) * 2;
            st[r0 * STG2 + c0]           = acc[am][an][0];
            st[r0 * STG2 + c0 + 1]       = acc[am][an][1];
            st[(r0 + 8) * STG2 + c0]     = acc[am][an][2];
            st[(r0 + 8) * STG2 + c0 + 1] = acc[am][an][3];
        }
    __syncthreads();
    #pragma unroll 4
    for (int i = 0; i < 16; i++) {
        int fid = i * 256 + tid;
        int r = fid >> 6, c4 = fid & 63;
        float4 v = *(const float4*)&st[r * STG2 + c4 * 4];
        *(float4*)&hp[((long)b * NN + rowBase + r) * DOUTT + c4 * 4] = v;
    }
}

// ---------------------------------------------------------------------------
extern "C" void kernel_launch(void* const* d_in, const int* in_sizes, int n_in,
                              void* d_out, int out_size)
{
    const float* h   = (const float*)d_in[0];
    const int*   adj = (const int*)  d_in[1];
    const int*   pos = (const int*)  d_in[2];
    const float* W   = (const float*)d_in[3];
    const float* a1  = (const float*)d_in[4];
    const float* a2  = (const float*)d_in[5];
    const float* pt  = (const float*)d_in[6];

    float* out = (float*)d_out;
    float* hp  = out;                              // [B,N,DOUT]
    float* att = out + (long)BB * NN * DOUTT;      // [B,N,N]

    static int smem_set = 0;
    if (!smem_set) {
        cudaFuncSetAttribute(g1_gemm, cudaFuncAttributeMaxDynamicSharedMemorySize, G1_SMEM);
        cudaFuncSetAttribute(g2_fused, cudaFuncAttributeMaxDynamicSharedMemorySize, G2_SMEM);
        smem_set = 1;
    }

    dim3 gT(DINN / 32, DOUTT / 32);                // (24, 8)
    k_transW<<<gT, 256>>>(W);

    dim3 gG(NN / 64, BB);                          // (8, 32) = 256 CTAs
    g1_gemm<<<gG, 256, G1_SMEM>>>(h, pos, pt, a1, a2);

    g2_fused<<<gG, 256, G2_SMEM>>>(adj, att, hp);
}